// round 15
// baseline (speedup 1.0000x reference)
#include <cuda_runtime.h>
#include <cuda_fp16.h>
#include <math.h>
#include <stdint.h>

#define T_SEQ   4096
#define C_DIM   1024
#define H_NUM   16
#define QKV_N   3072

// Q pre-scale: 1/sqrt(64) * log2(e)  (softmax in base-2 domain)
#define QSCALE 0.1803368801111204f

// Scratch (device globals; allocation-free per harness rules)
__device__ __half g_xh[(size_t)T_SEQ * C_DIM];          // 8 MB x fp16
__device__ __half g_wqh[(size_t)C_DIM * QKV_N];         // 6 MB W_qkv fp16
__device__ __half g_woh[(size_t)C_DIM * C_DIM];         // 2 MB W_out fp16
__device__ __half g_qh[(size_t)T_SEQ * C_DIM];          // 8 MB Q fp16 (pre-scaled)
__device__ __half g_kh[(size_t)T_SEQ * C_DIM];          // 8 MB K fp16
__device__ __half g_vt[(size_t)H_NUM * 64 * T_SEQ];     // 8 MB V fp16, [h][dh][T]
__device__ __half g_ao[(size_t)T_SEQ * C_DIM];          // 8 MB attention out fp16

__device__ __forceinline__ float ex2f(float x) {
    float y;
    asm("ex2.approx.f32 %0, %1;" : "=f"(y) : "f"(x));
    return y;
}

__device__ __forceinline__ void mma_f16(float* c, const unsigned* a, const unsigned* b) {
    asm volatile(
        "mma.sync.aligned.m16n8k16.row.col.f32.f16.f16.f32 "
        "{%0,%1,%2,%3},{%4,%5,%6,%7},{%8,%9},{%0,%1,%2,%3};"
        : "+f"(c[0]), "+f"(c[1]), "+f"(c[2]), "+f"(c[3])
        : "r"(a[0]), "r"(a[1]), "r"(a[2]), "r"(a[3]),
          "r"(b[0]), "r"(b[1]));
}

// fp16-accumulator variant: D/C are 2 packed f16x2 regs.
// d0 = {pos0, pos1} (same element positions as f32 c0,c1), d1 = {pos2, pos3}.
__device__ __forceinline__ void mma_f16acc(unsigned* c, const unsigned* a, const unsigned* b) {
    asm volatile(
        "mma.sync.aligned.m16n8k16.row.col.f16.f16.f16.f16 "
        "{%0,%1},{%2,%3,%4,%5},{%6,%7},{%0,%1};"
        : "+r"(c[0]), "+r"(c[1])
        : "r"(a[0]), "r"(a[1]), "r"(a[2]), "r"(a[3]),
          "r"(b[0]), "r"(b[1]));
}

__device__ __forceinline__ void ldsm_x4(unsigned& r0, unsigned& r1,
                                        unsigned& r2, unsigned& r3, uint32_t addr) {
    asm volatile("ldmatrix.sync.aligned.m8n8.x4.shared.b16 {%0,%1,%2,%3}, [%4];"
                 : "=r"(r0), "=r"(r1), "=r"(r2), "=r"(r3) : "r"(addr));
}

__device__ __forceinline__ void ldsm_x4t(unsigned& r0, unsigned& r1,
                                         unsigned& r2, unsigned& r3, uint32_t addr) {
    asm volatile("ldmatrix.sync.aligned.m8n8.x4.trans.shared.b16 {%0,%1,%2,%3}, [%4];"
                 : "=r"(r0), "=r"(r1), "=r"(r2), "=r"(r3) : "r"(addr));
}

__device__ __forceinline__ void cp16(uint32_t dst, const void* src) {
    asm volatile("cp.async.cg.shared.global [%0], [%1], 16;" :: "r"(dst), "l"(src));
}
#define CP_COMMIT() asm volatile("cp.async.commit_group;" ::: "memory")

// ---------------------------------------------------------------------------
// Fused prepass: one launch converts x, W_qkv, W_out fp32 -> fp16.
// ---------------------------------------------------------------------------
#define N8_X   (T_SEQ * C_DIM / 8)
#define N8_WQ  (C_DIM * QKV_N / 8)
#define N8_WO  (C_DIM * C_DIM / 8)
#define N8_TOT (N8_X + N8_WQ + N8_WO)

__global__ __launch_bounds__(256) void cvt_all_kernel(
    const float4* __restrict__ x, const float4* __restrict__ wq,
    const float4* __restrict__ wo,
    uint4* __restrict__ xh, uint4* __restrict__ wqh, uint4* __restrict__ woh)
{
    int i = blockIdx.x * 256 + threadIdx.x;
    if (i >= N8_TOT) return;
    const float4* src;
    uint4* dst;
    int j;
    if (i < N8_X)              { src = x;  dst = xh;  j = i; }
    else if (i < N8_X + N8_WQ) { src = wq; dst = wqh; j = i - N8_X; }
    else                       { src = wo; dst = woh; j = i - N8_X - N8_WQ; }
    float4 v0 = src[2 * j];
    float4 v1 = src[2 * j + 1];
    __half2 h0 = __floats2half2_rn(v0.x, v0.y);
    __half2 h1 = __floats2half2_rn(v0.z, v0.w);
    __half2 h2 = __floats2half2_rn(v1.x, v1.y);
    __half2 h3 = __floats2half2_rn(v1.z, v1.w);
    uint4 u;
    u.x = *(unsigned*)&h0; u.y = *(unsigned*)&h1;
    u.z = *(unsigned*)&h2; u.w = *(unsigned*)&h3;
    dst[j] = u;
}

// ---------------------------------------------------------------------------
// fp16 GEMM (R11/R14 config, unchanged): 128x128 tile, BK=32, 4-stage
// cp.async, 256 threads, warp tile 32x64.
// ---------------------------------------------------------------------------
#define GBM 128
#define GBN 128
#define GBK 32
#define SAH 40
#define SBH 136
#define STAGE_AH (GBM * SAH)
#define STAGE_BH (GBK * SBH)
#define GEMM_NSTAGE 4
#define GEMM_SMEM_BYTES (GEMM_NSTAGE * (STAGE_AH + STAGE_BH) * 2)

__global__ __launch_bounds__(256, 2) void gemm_f16(
    const __half* __restrict__ A, const __half* __restrict__ B,
    const float* __restrict__ bias, float* __restrict__ C,
    int M, int N, int K, int mode,
    __half* __restrict__ qh, __half* __restrict__ kh, __half* __restrict__ vt)
{
    extern __shared__ __half gsm[];
    __half* As = gsm;
    __half* Bs = gsm + GEMM_NSTAGE * STAGE_AH;
    const uint32_t as_u = (uint32_t)__cvta_generic_to_shared(As);
    const uint32_t bs_u = (uint32_t)__cvta_generic_to_shared(Bs);

    const int tid  = threadIdx.x;
    const int lane = tid & 31;
    const int warp = tid >> 5;
    const int wm   = warp & 3;
    const int wn   = warp >> 2;
    const int r    = lane >> 2;
    const int q    = lane & 3;
    const int bm   = blockIdx.y * GBM;
    const int bn   = blockIdx.x * GBN;

    const int ar0 = tid >> 2;
    const int acg = (tid & 3) * 8;
    const int bk0 = tid >> 4;
    const int bng = (tid & 15) * 8;

    const int nslab = K / GBK;

    auto stage = [&](int slab) {
        const int buf = slab & 3;
        const uint32_t ad = as_u + (uint32_t)(buf * STAGE_AH) * 2;
        const uint32_t bd = bs_u + (uint32_t)(buf * STAGE_BH) * 2;
        const int koff = slab * GBK;
        cp16(ad + (uint32_t)(ar0 * SAH + acg) * 2,
             A + (size_t)(bm + ar0) * K + koff + acg);
        cp16(ad + (uint32_t)((ar0 + 64) * SAH + acg) * 2,
             A + (size_t)(bm + ar0 + 64) * K + koff + acg);
        cp16(bd + (uint32_t)(bk0 * SBH + bng) * 2,
             B + (size_t)(koff + bk0) * N + bn + bng);
        cp16(bd + (uint32_t)((bk0 + 16) * SBH + bng) * 2,
             B + (size_t)(koff + bk0 + 16) * N + bn + bng);
        CP_COMMIT();
    };

    const uint32_t a_lrow = (uint32_t)(wm * 32 + (lane & 15));
    const uint32_t a_lcol = (uint32_t)(8 * (lane >> 4));
    const uint32_t b_lk = (uint32_t)((lane & 7) + 8 * ((lane >> 3) & 1));
    const uint32_t b_ln = (uint32_t)(wn * 64 + 8 * ((lane >> 4) & 1));

    float acc[2][8][4];
    #pragma unroll
    for (int i = 0; i < 2; i++)
        #pragma unroll
        for (int j = 0; j < 8; j++)
            #pragma unroll
            for (int k = 0; k < 4; k++) acc[i][j][k] = 0.0f;

    stage(0); stage(1); stage(2);

    #pragma unroll 1
    for (int i = 0; i < nslab; i++) {
        if (i + 2 < nslab) {
            asm volatile("cp.async.wait_group 2;" ::: "memory");
        } else {
            asm volatile("cp.async.wait_group 0;" ::: "memory");
        }
        __syncthreads();

        if (i + 3 < nslab) stage(i + 3);

        const int buf = i & 3;
        const uint32_t ab = as_u + (uint32_t)(buf * STAGE_AH) * 2;
        const uint32_t bb = bs_u + (uint32_t)(buf * STAGE_BH) * 2;

        #pragma unroll
        for (int kk = 0; kk < GBK; kk += 16) {
            unsigned af[2][4];
            #pragma unroll
            for (int mt = 0; mt < 2; mt++) {
                ldsm_x4(af[mt][0], af[mt][1], af[mt][2], af[mt][3],
                        ab + ((a_lrow + mt * 16) * SAH + kk + a_lcol) * 2);
            }
            #pragma unroll
            for (int np = 0; np < 4; np++) {
                unsigned b0, b1, b2, b3;
                ldsm_x4t(b0, b1, b2, b3,
                         bb + ((kk + b_lk) * SBH + b_ln + np * 16) * 2);
                unsigned bfa[2] = {b0, b1};
                unsigned bfb[2] = {b2, b3};
                mma_f16(acc[0][2 * np],     af[0], bfa);
                mma_f16(acc[0][2 * np + 1], af[0], bfb);
                mma_f16(acc[1][2 * np],     af[1], bfa);
                mma_f16(acc[1][2 * np + 1], af[1], bfb);
            }
        }
    }

    // epilogue
    #pragma unroll
    for (int mt = 0; mt < 2; mt++) {
        const int row = bm + wm * 32 + mt * 16 + r;
        #pragma unroll
        for (int nt = 0; nt < 8; nt++) {
            const int col = bn + wn * 64 + nt * 8 + 2 * q;
            const float b0 = bias[col], b1 = bias[col + 1];
            float v00 = acc[mt][nt][0] + b0, v01 = acc[mt][nt][1] + b1;
            float v10 = acc[mt][nt][2] + b0, v11 = acc[mt][nt][3] + b1;
            if (mode == 0) {
                *(float2*)(C + (size_t)row * N + col)       = make_float2(v00, v01);
                *(float2*)(C + (size_t)(row + 8) * N + col) = make_float2(v10, v11);
            } else if (col < C_DIM) {
                __half2 h0 = __floats2half2_rn(v00 * QSCALE, v01 * QSCALE);
                __half2 h1 = __floats2half2_rn(v10 * QSCALE, v11 * QSCALE);
                *(__half2*)(qh + (size_t)row * C_DIM + col)       = h0;
                *(__half2*)(qh + (size_t)(row + 8) * C_DIM + col) = h1;
            } else if (col < 2 * C_DIM) {
                __half2 h0 = __floats2half2_rn(v00, v01);
                __half2 h1 = __floats2half2_rn(v10, v11);
                *(__half2*)(kh + (size_t)row * C_DIM + col - C_DIM)       = h0;
                *(__half2*)(kh + (size_t)(row + 8) * C_DIM + col - C_DIM) = h1;
            } else {
                const int d = col - 2 * C_DIM;
                vt[(size_t)d * T_SEQ + row]           = __float2half_rn(v00);
                vt[(size_t)(d + 1) * T_SEQ + row]     = __float2half_rn(v01);
                vt[(size_t)d * T_SEQ + row + 8]       = __float2half_rn(v10);
                vt[(size_t)(d + 1) * T_SEQ + row + 8] = __float2half_rn(v11);
            }
        }
    }
}

// ---------------------------------------------------------------------------
// Flash attention: fp16 QK^T (f32 acc, unchanged) + PV with f16 ACCUMULATORS
// (per-tile f16 partial, promoted to fp32 master O each tile).
// 256 threads = 8 warps x 16 q rows = 128 q rows/block.
// ---------------------------------------------------------------------------
#define AST 72
#define TILE_H (64 * AST)
#define ATTN_SMEM_BYTES (4 * TILE_H * 2)

__global__ __launch_bounds__(256, 2) void attn_f16(
    const __half* __restrict__ qh, const __half* __restrict__ kh,
    const __half* __restrict__ vt, __half* __restrict__ attn_out)
{
    extern __shared__ __half hsm[];
    __half* Ksb = hsm;                    // [2][64][AST]
    __half* Vsb = hsm + 2 * TILE_H;       // [2][64][AST]
    const uint32_t ks_u = (uint32_t)__cvta_generic_to_shared(Ksb);
    const uint32_t vs_u = (uint32_t)__cvta_generic_to_shared(Vsb);

    const int h    = blockIdx.y;
    const int qb   = blockIdx.x;
    const int tid  = threadIdx.x;
    const int lane = tid & 31;
    const int warp = tid >> 5;
    const int r    = lane >> 2;
    const int q    = lane & 3;

    const int rowin = lane & 7;
    const int kb8   = (lane >> 3) & 1;
    const int nt8   = (lane >> 4) & 1;
    const uint32_t ldsm_off = (uint32_t)(((nt8 * 8 + rowin) * AST + kb8 * 8) * 2);

    unsigned qa[4][4];
    const int qrow = qb * 128 + warp * 16 + r;
    const __half* qp0 = qh + (size_t)qrow * C_DIM + h * 64;
    const __half* qp1 = qp0 + (size_t)8 * C_DIM;
    #pragma unroll
    for (int ks = 0; ks < 4; ks++) {
        qa[ks][0] = *(const unsigned*)(qp0 + 16 * ks + 2 * q);
        qa[ks][1] = *(const unsigned*)(qp1 + 16 * ks + 2 * q);
        qa[ks][2] = *(const unsigned*)(qp0 + 16 * ks + 2 * q + 8);
        qa[ks][3] = *(const unsigned*)(qp1 + 16 * ks + 2 * q + 8);
    }

    float o[8][4];
    #pragma unroll
    for (int nt = 0; nt < 8; nt++)
        #pragma unroll
        for (int i = 0; i < 4; i++) o[nt][i] = 0.0f;
    float m0 = -INFINITY, m1 = -INFINITY;
    float l0 = 0.0f, l1 = 0.0f;

    auto stage = [&](int kb, int buf) {
        const uint32_t kd = ks_u + (uint32_t)buf * TILE_H * 2;
        const uint32_t vd = vs_u + (uint32_t)buf * TILE_H * 2;
        #pragma unroll
        for (int i = 0; i < 2; i++) {
            const int chunk = tid + i * 256;
            const int row = chunk >> 3;
            const int c   = chunk & 7;
            cp16(kd + (uint32_t)(row * AST) * 2 + c * 16,
                 kh + (size_t)(kb * 64 + row) * C_DIM + h * 64 + c * 8);
            cp16(vd + (uint32_t)(row * AST) * 2 + c * 16,
                 vt + (size_t)(h * 64 + row) * T_SEQ + kb * 64 + c * 8);
        }
        CP_COMMIT();
    };

    stage(0, 0);

    #pragma unroll 1
    for (int kb = 0; kb < T_SEQ / 64; kb++) {
        const int cur = kb & 1;
        asm volatile("cp.async.wait_group 0;" ::: "memory");
        __syncthreads();
        if (kb + 1 < T_SEQ / 64) stage(kb + 1, cur ^ 1);

        const uint32_t kbase = ks_u + (uint32_t)cur * TILE_H * 2 + ldsm_off;
        const uint32_t vbase = vs_u + (uint32_t)cur * TILE_H * 2 + ldsm_off;

        // S = Q @ K^T (f32 acc — precision required)
        float p[8][4];
        #pragma unroll
        for (int nt = 0; nt < 8; nt++)
            #pragma unroll
            for (int i = 0; i < 4; i++) p[nt][i] = 0.0f;

        #pragma unroll
        for (int ks = 0; ks < 4; ks++) {
            #pragma unroll
            for (int pp = 0; pp < 4; pp++) {
                unsigned b0, b1, b2, b3;
                ldsm_x4(b0, b1, b2, b3,
                        kbase + (uint32_t)((pp * 16 * AST + ks * 16) * 2));
                unsigned bfa[2] = {b0, b1};
                unsigned bfb[2] = {b2, b3};
                mma_f16(p[2 * pp],     qa[ks], bfa);
                mma_f16(p[2 * pp + 1], qa[ks], bfb);
            }
        }

        // online softmax (base 2)
        float mx0 = -INFINITY, mx1 = -INFINITY;
        #pragma unroll
        for (int nt = 0; nt < 8; nt++) {
            mx0 = fmaxf(mx0, fmaxf(p[nt][0], p[nt][1]));
            mx1 = fmaxf(mx1, fmaxf(p[nt][2], p[nt][3]));
        }
        #pragma unroll
        for (int off = 1; off < 4; off <<= 1) {
            mx0 = fmaxf(mx0, __shfl_xor_sync(0xffffffffu, mx0, off));
            mx1 = fmaxf(mx1, __shfl_xor_sync(0xffffffffu, mx1, off));
        }
        const float nm0 = fmaxf(m0, mx0);
        const float nm1 = fmaxf(m1, mx1);
        const float al0 = ex2f(m0 - nm0);
        const float al1 = ex2f(m1 - nm1);
        m0 = nm0; m1 = nm1;

        float rs0 = 0.0f, rs1 = 0.0f;
        #pragma unroll
        for (int nt = 0; nt < 8; nt++) {
            p[nt][0] = ex2f(p[nt][0] - m0);
            p[nt][1] = ex2f(p[nt][1] - m0);
            p[nt][2] = ex2f(p[nt][2] - m1);
            p[nt][3] = ex2f(p[nt][3] - m1);
            rs0 += p[nt][0] + p[nt][1];
            rs1 += p[nt][2] + p[nt][3];
        }
        l0 = l0 * al0 + rs0;
        l1 = l1 * al1 + rs1;

        if (__any_sync(0xffffffffu, (al0 < 1.0f) || (al1 < 1.0f))) {
            #pragma unroll
            for (int nt = 0; nt < 8; nt++) {
                o[nt][0] *= al0; o[nt][1] *= al0;
                o[nt][2] *= al1; o[nt][3] *= al1;
            }
        }

        // O_tile = P @ V with f16 accumulators (testing 2x HMMA.F16 rate),
        // then promote tile partial to fp32 master O.
        unsigned hc[8][2];
        #pragma unroll
        for (int nt = 0; nt < 8; nt++) { hc[nt][0] = 0u; hc[nt][1] = 0u; }

        #pragma unroll
        for (int ks = 0; ks < 4; ks++) {
            unsigned af[4];
            __half2 t0 = __floats2half2_rn(p[2 * ks][0],     p[2 * ks][1]);
            __half2 t1 = __floats2half2_rn(p[2 * ks][2],     p[2 * ks][3]);
            __half2 t2 = __floats2half2_rn(p[2 * ks + 1][0], p[2 * ks + 1][1]);
            __half2 t3 = __floats2half2_rn(p[2 * ks + 1][2], p[2 * ks + 1][3]);
            af[0] = *(unsigned*)&t0;
            af[1] = *(unsigned*)&t1;
            af[2] = *(unsigned*)&t2;
            af[3] = *(unsigned*)&t3;
            #pragma unroll
            for (int pt = 0; pt < 4; pt++) {
                unsigned b0, b1, b2, b3;
                ldsm_x4(b0, b1, b2, b3,
                        vbase + (uint32_t)((pt * 16 * AST + ks * 16) * 2));
                unsigned bfa[2] = {b0, b1};
                unsigned bfb[2] = {b2, b3};
                mma_f16acc(hc[2 * pt],     af, bfa);
                mma_f16acc(hc[2 * pt + 1], af, bfb);
            }
        }

        // promote f16 tile partials to fp32 master
        #pragma unroll
        for (int nt = 0; nt < 8; nt++) {
            float2 lo = __half22float2(*(__half2*)&hc[nt][0]);
            float2 hi = __half22float2(*(__half2*)&hc[nt][1]);
            o[nt][0] += lo.x; o[nt][1] += lo.y;
            o[nt][2] += hi.x; o[nt][3] += hi.y;
        }
    }

    #pragma unroll
    for (int off = 1; off < 4; off <<= 1) {
        l0 += __shfl_xor_sync(0xffffffffu, l0, off);
        l1 += __shfl_xor_sync(0xffffffffu, l1, off);
    }
    const float il0 = 1.0f / l0;
    const float il1 = 1.0f / l1;
    __half* op0 = attn_out + (size_t)qrow * C_DIM + h * 64;
    __half* op1 = op0 + (size_t)8 * C_DIM;
    #pragma unroll
    for (int nt = 0; nt < 8; nt++) {
        const int col = nt * 8 + 2 * q;
        *(__half2*)(op0 + col) = __floats2half2_rn(o[nt][0] * il0, o[nt][1] * il0);
        *(__half2*)(op1 + col) = __floats2half2_rn(o[nt][2] * il1, o[nt][3] * il1);
    }
}

// ---------------------------------------------------------------------------
extern "C" void kernel_launch(void* const* d_in, const int* in_sizes, int n_in,
                              void* d_out, int out_size)
{
    const float* x    = (const float*)d_in[0];
    const float* Wqkv = (const float*)d_in[1];
    const float* bqkv = (const float*)d_in[2];
    const float* Wout = (const float*)d_in[3];
    const float* bout = (const float*)d_in[4];
    float* out = (float*)d_out;

    __half *xh, *wqh, *woh, *qh, *kh, *vt, *ao;
    cudaGetSymbolAddress((void**)&xh,  g_xh);
    cudaGetSymbolAddress((void**)&wqh, g_wqh);
    cudaGetSymbolAddress((void**)&woh, g_woh);
    cudaGetSymbolAddress((void**)&qh,  g_qh);
    cudaGetSymbolAddress((void**)&kh,  g_kh);
    cudaGetSymbolAddress((void**)&vt,  g_vt);
    cudaGetSymbolAddress((void**)&ao,  g_ao);

    cudaFuncSetAttribute(gemm_f16, cudaFuncAttributeMaxDynamicSharedMemorySize,
                         GEMM_SMEM_BYTES);
    cudaFuncSetAttribute(attn_f16, cudaFuncAttributeMaxDynamicSharedMemorySize,
                         ATTN_SMEM_BYTES);

    // 0) fused prepass: fp32 -> fp16 (one launch)
    cvt_all_kernel<<<(N8_TOT + 255) / 256, 256>>>(
        (const float4*)x, (const float4*)Wqkv, (const float4*)Wout,
        (uint4*)xh, (uint4*)wqh, (uint4*)woh);

    // 1) QKV projection (fp16 mma) -> fp16 Q/K/V (V head-transposed)
    gemm_f16<<<dim3(QKV_N / GBN, T_SEQ / GBM), 256, GEMM_SMEM_BYTES>>>(
        xh, wqh, bqkv, nullptr, T_SEQ, QKV_N, C_DIM, 1, qh, kh, vt);

    // 2) Multi-head flash attention (PV with f16 accumulators)
    attn_f16<<<dim3(T_SEQ / 128, H_NUM), 256, ATTN_SMEM_BYTES>>>(qh, kh, vt, ao);

    // 3) Output projection (fp16 mma, fp32 out)
    gemm_f16<<<dim3(C_DIM / GBN, T_SEQ / GBM), 256, GEMM_SMEM_BYTES>>>(
        ao, woh, bout, out, T_SEQ, C_DIM, C_DIM, 0,
        nullptr, nullptr, nullptr);
}

// round 16
// speedup vs baseline: 1.0263x; 1.0263x over previous
#include <cuda_runtime.h>
#include <cuda_fp16.h>
#include <math.h>
#include <stdint.h>

// ============================================================================
// FullAttention — final kernel (R14 configuration, banked).
//
// Pipeline: fused fp32->fp16 prepass (1 launch) -> fp16 mma.sync QKV GEMM
// (split epilogue: Q pre-scaled by 1/8*log2e, K, V head-transposed) ->
// fp16 flash attention (base-2 softmax, register P, ldmatrix operands,
// cp.async double buffering) -> fp16 mma.sync output GEMM (fp32 out).
//
// Performance model (validated over 15 rounds): the sm_103 fallback HMMA
// path issues mma.sync at ~17.8 cyc/instr/SMSP regardless of shape/accum/
// occupancy. Total 25.2M mma -> ~379us floor; this kernel measures ~389us.
// ============================================================================

#define T_SEQ   4096
#define C_DIM   1024
#define H_NUM   16
#define QKV_N   3072

// Q pre-scale: 1/sqrt(64) * log2(e)  (softmax in base-2 domain)
#define QSCALE 0.1803368801111204f

// Scratch (device globals; allocation-free per harness rules)
__device__ __half g_xh[(size_t)T_SEQ * C_DIM];          // 8 MB x fp16
__device__ __half g_wqh[(size_t)C_DIM * QKV_N];         // 6 MB W_qkv fp16
__device__ __half g_woh[(size_t)C_DIM * C_DIM];         // 2 MB W_out fp16
__device__ __half g_qh[(size_t)T_SEQ * C_DIM];          // 8 MB Q fp16 (pre-scaled)
__device__ __half g_kh[(size_t)T_SEQ * C_DIM];          // 8 MB K fp16
__device__ __half g_vt[(size_t)H_NUM * 64 * T_SEQ];     // 8 MB V fp16, [h][dh][T]
__device__ __half g_ao[(size_t)T_SEQ * C_DIM];          // 8 MB attention out fp16

__device__ __forceinline__ float ex2f(float x) {
    float y;
    asm("ex2.approx.f32 %0, %1;" : "=f"(y) : "f"(x));
    return y;
}

__device__ __forceinline__ void mma_f16(float* c, const unsigned* a, const unsigned* b) {
    asm volatile(
        "mma.sync.aligned.m16n8k16.row.col.f32.f16.f16.f32 "
        "{%0,%1,%2,%3},{%4,%5,%6,%7},{%8,%9},{%0,%1,%2,%3};"
        : "+f"(c[0]), "+f"(c[1]), "+f"(c[2]), "+f"(c[3])
        : "r"(a[0]), "r"(a[1]), "r"(a[2]), "r"(a[3]),
          "r"(b[0]), "r"(b[1]));
}

__device__ __forceinline__ void ldsm_x4(unsigned& r0, unsigned& r1,
                                        unsigned& r2, unsigned& r3, uint32_t addr) {
    asm volatile("ldmatrix.sync.aligned.m8n8.x4.shared.b16 {%0,%1,%2,%3}, [%4];"
                 : "=r"(r0), "=r"(r1), "=r"(r2), "=r"(r3) : "r"(addr));
}

__device__ __forceinline__ void ldsm_x4t(unsigned& r0, unsigned& r1,
                                         unsigned& r2, unsigned& r3, uint32_t addr) {
    asm volatile("ldmatrix.sync.aligned.m8n8.x4.trans.shared.b16 {%0,%1,%2,%3}, [%4];"
                 : "=r"(r0), "=r"(r1), "=r"(r2), "=r"(r3) : "r"(addr));
}

__device__ __forceinline__ void cp16(uint32_t dst, const void* src) {
    asm volatile("cp.async.cg.shared.global [%0], [%1], 16;" :: "r"(dst), "l"(src));
}
#define CP_COMMIT() asm volatile("cp.async.commit_group;" ::: "memory")

// ---------------------------------------------------------------------------
// Fused prepass: one launch converts x, W_qkv, W_out fp32 -> fp16.
// ---------------------------------------------------------------------------
#define N8_X   (T_SEQ * C_DIM / 8)
#define N8_WQ  (C_DIM * QKV_N / 8)
#define N8_WO  (C_DIM * C_DIM / 8)
#define N8_TOT (N8_X + N8_WQ + N8_WO)

__global__ __launch_bounds__(256) void cvt_all_kernel(
    const float4* __restrict__ x, const float4* __restrict__ wq,
    const float4* __restrict__ wo,
    uint4* __restrict__ xh, uint4* __restrict__ wqh, uint4* __restrict__ woh)
{
    int i = blockIdx.x * 256 + threadIdx.x;
    if (i >= N8_TOT) return;
    const float4* src;
    uint4* dst;
    int j;
    if (i < N8_X)              { src = x;  dst = xh;  j = i; }
    else if (i < N8_X + N8_WQ) { src = wq; dst = wqh; j = i - N8_X; }
    else                       { src = wo; dst = woh; j = i - N8_X - N8_WQ; }
    float4 v0 = src[2 * j];
    float4 v1 = src[2 * j + 1];
    __half2 h0 = __floats2half2_rn(v0.x, v0.y);
    __half2 h1 = __floats2half2_rn(v0.z, v0.w);
    __half2 h2 = __floats2half2_rn(v1.x, v1.y);
    __half2 h3 = __floats2half2_rn(v1.z, v1.w);
    uint4 u;
    u.x = *(unsigned*)&h0; u.y = *(unsigned*)&h1;
    u.z = *(unsigned*)&h2; u.w = *(unsigned*)&h3;
    dst[j] = u;
}

// ---------------------------------------------------------------------------
// fp16 GEMM: 128x128 tile, BK=32, 4-stage cp.async, 256 threads, 8 warps
// (4m x 2n), warp tile 32x64. A smem [128][SAH], B smem [32][SBH]
// (ldsm x4 / x4.trans). mode 0: fp32 out. mode 1: QKV split epilogue.
// ---------------------------------------------------------------------------
#define GBM 128
#define GBN 128
#define GBK 32
#define SAH 40
#define SBH 136
#define STAGE_AH (GBM * SAH)
#define STAGE_BH (GBK * SBH)
#define GEMM_NSTAGE 4
#define GEMM_SMEM_BYTES (GEMM_NSTAGE * (STAGE_AH + STAGE_BH) * 2)   // 75776 B

__global__ __launch_bounds__(256, 2) void gemm_f16(
    const __half* __restrict__ A, const __half* __restrict__ B,
    const float* __restrict__ bias, float* __restrict__ C,
    int M, int N, int K, int mode,
    __half* __restrict__ qh, __half* __restrict__ kh, __half* __restrict__ vt)
{
    extern __shared__ __half gsm[];
    __half* As = gsm;                                   // [4][128][SAH]
    __half* Bs = gsm + GEMM_NSTAGE * STAGE_AH;          // [4][32][SBH]
    const uint32_t as_u = (uint32_t)__cvta_generic_to_shared(As);
    const uint32_t bs_u = (uint32_t)__cvta_generic_to_shared(Bs);

    const int tid  = threadIdx.x;
    const int lane = tid & 31;
    const int warp = tid >> 5;
    const int wm   = warp & 3;
    const int wn   = warp >> 2;
    const int r    = lane >> 2;
    const int q    = lane & 3;
    const int bm   = blockIdx.y * GBM;
    const int bn   = blockIdx.x * GBN;

    const int ar0 = tid >> 2;
    const int acg = (tid & 3) * 8;
    const int bk0 = tid >> 4;
    const int bng = (tid & 15) * 8;

    const int nslab = K / GBK;

    auto stage = [&](int slab) {
        const int buf = slab & 3;
        const uint32_t ad = as_u + (uint32_t)(buf * STAGE_AH) * 2;
        const uint32_t bd = bs_u + (uint32_t)(buf * STAGE_BH) * 2;
        const int koff = slab * GBK;
        cp16(ad + (uint32_t)(ar0 * SAH + acg) * 2,
             A + (size_t)(bm + ar0) * K + koff + acg);
        cp16(ad + (uint32_t)((ar0 + 64) * SAH + acg) * 2,
             A + (size_t)(bm + ar0 + 64) * K + koff + acg);
        cp16(bd + (uint32_t)(bk0 * SBH + bng) * 2,
             B + (size_t)(koff + bk0) * N + bn + bng);
        cp16(bd + (uint32_t)((bk0 + 16) * SBH + bng) * 2,
             B + (size_t)(koff + bk0 + 16) * N + bn + bng);
        CP_COMMIT();
    };

    const uint32_t a_lrow = (uint32_t)(wm * 32 + (lane & 15));
    const uint32_t a_lcol = (uint32_t)(8 * (lane >> 4));
    const uint32_t b_lk = (uint32_t)((lane & 7) + 8 * ((lane >> 3) & 1));
    const uint32_t b_ln = (uint32_t)(wn * 64 + 8 * ((lane >> 4) & 1));

    float acc[2][8][4];
    #pragma unroll
    for (int i = 0; i < 2; i++)
        #pragma unroll
        for (int j = 0; j < 8; j++)
            #pragma unroll
            for (int k = 0; k < 4; k++) acc[i][j][k] = 0.0f;

    stage(0); stage(1); stage(2);

    #pragma unroll 1
    for (int i = 0; i < nslab; i++) {
        if (i + 2 < nslab) {
            asm volatile("cp.async.wait_group 2;" ::: "memory");
        } else {
            asm volatile("cp.async.wait_group 0;" ::: "memory");
        }
        __syncthreads();

        if (i + 3 < nslab) stage(i + 3);

        const int buf = i & 3;
        const uint32_t ab = as_u + (uint32_t)(buf * STAGE_AH) * 2;
        const uint32_t bb = bs_u + (uint32_t)(buf * STAGE_BH) * 2;

        #pragma unroll
        for (int kk = 0; kk < GBK; kk += 16) {
            unsigned af[2][4];
            #pragma unroll
            for (int mt = 0; mt < 2; mt++) {
                ldsm_x4(af[mt][0], af[mt][1], af[mt][2], af[mt][3],
                        ab + ((a_lrow + mt * 16) * SAH + kk + a_lcol) * 2);
            }
            #pragma unroll
            for (int np = 0; np < 4; np++) {
                unsigned b0, b1, b2, b3;
                ldsm_x4t(b0, b1, b2, b3,
                         bb + ((kk + b_lk) * SBH + b_ln + np * 16) * 2);
                unsigned bfa[2] = {b0, b1};
                unsigned bfb[2] = {b2, b3};
                mma_f16(acc[0][2 * np],     af[0], bfa);
                mma_f16(acc[0][2 * np + 1], af[0], bfb);
                mma_f16(acc[1][2 * np],     af[1], bfa);
                mma_f16(acc[1][2 * np + 1], af[1], bfb);
            }
        }
    }

    // epilogue
    #pragma unroll
    for (int mt = 0; mt < 2; mt++) {
        const int row = bm + wm * 32 + mt * 16 + r;
        #pragma unroll
        for (int nt = 0; nt < 8; nt++) {
            const int col = bn + wn * 64 + nt * 8 + 2 * q;
            const float b0 = bias[col], b1 = bias[col + 1];
            float v00 = acc[mt][nt][0] + b0, v01 = acc[mt][nt][1] + b1;
            float v10 = acc[mt][nt][2] + b0, v11 = acc[mt][nt][3] + b1;
            if (mode == 0) {
                *(float2*)(C + (size_t)row * N + col)       = make_float2(v00, v01);
                *(float2*)(C + (size_t)(row + 8) * N + col) = make_float2(v10, v11);
            } else if (col < C_DIM) {
                __half2 h0 = __floats2half2_rn(v00 * QSCALE, v01 * QSCALE);
                __half2 h1 = __floats2half2_rn(v10 * QSCALE, v11 * QSCALE);
                *(__half2*)(qh + (size_t)row * C_DIM + col)       = h0;
                *(__half2*)(qh + (size_t)(row + 8) * C_DIM + col) = h1;
            } else if (col < 2 * C_DIM) {
                __half2 h0 = __floats2half2_rn(v00, v01);
                __half2 h1 = __floats2half2_rn(v10, v11);
                *(__half2*)(kh + (size_t)row * C_DIM + col - C_DIM)       = h0;
                *(__half2*)(kh + (size_t)(row + 8) * C_DIM + col - C_DIM) = h1;
            } else {
                const int d = col - 2 * C_DIM;
                vt[(size_t)d * T_SEQ + row]           = __float2half_rn(v00);
                vt[(size_t)(d + 1) * T_SEQ + row]     = __float2half_rn(v01);
                vt[(size_t)d * T_SEQ + row + 8]       = __float2half_rn(v10);
                vt[(size_t)(d + 1) * T_SEQ + row + 8] = __float2half_rn(v11);
            }
        }
    }
}

// ---------------------------------------------------------------------------
// Flash attention: fp16 m16n8k16 mma (f32 accum), ldmatrix b-frags,
// base-2 softmax, deferred l-reduction, conditional rescale.
// 256 threads = 8 warps x 16 q rows = 128 q rows/block. fp16 output.
// ---------------------------------------------------------------------------
#define AST 72
#define TILE_H (64 * AST)
#define ATTN_SMEM_BYTES (4 * TILE_H * 2)

__global__ __launch_bounds__(256, 2) void attn_f16(
    const __half* __restrict__ qh, const __half* __restrict__ kh,
    const __half* __restrict__ vt, __half* __restrict__ attn_out)
{
    extern __shared__ __half hsm[];
    __half* Ksb = hsm;                    // [2][64][AST]
    __half* Vsb = hsm + 2 * TILE_H;       // [2][64][AST]
    const uint32_t ks_u = (uint32_t)__cvta_generic_to_shared(Ksb);
    const uint32_t vs_u = (uint32_t)__cvta_generic_to_shared(Vsb);

    const int h    = blockIdx.y;
    const int qb   = blockIdx.x;
    const int tid  = threadIdx.x;
    const int lane = tid & 31;
    const int warp = tid >> 5;
    const int r    = lane >> 2;
    const int q    = lane & 3;

    const int rowin = lane & 7;
    const int kb8   = (lane >> 3) & 1;
    const int nt8   = (lane >> 4) & 1;
    const uint32_t ldsm_off = (uint32_t)(((nt8 * 8 + rowin) * AST + kb8 * 8) * 2);

    unsigned qa[4][4];
    const int qrow = qb * 128 + warp * 16 + r;
    const __half* qp0 = qh + (size_t)qrow * C_DIM + h * 64;
    const __half* qp1 = qp0 + (size_t)8 * C_DIM;
    #pragma unroll
    for (int ks = 0; ks < 4; ks++) {
        qa[ks][0] = *(const unsigned*)(qp0 + 16 * ks + 2 * q);
        qa[ks][1] = *(const unsigned*)(qp1 + 16 * ks + 2 * q);
        qa[ks][2] = *(const unsigned*)(qp0 + 16 * ks + 2 * q + 8);
        qa[ks][3] = *(const unsigned*)(qp1 + 16 * ks + 2 * q + 8);
    }

    float o[8][4];
    #pragma unroll
    for (int nt = 0; nt < 8; nt++)
        #pragma unroll
        for (int i = 0; i < 4; i++) o[nt][i] = 0.0f;
    float m0 = -INFINITY, m1 = -INFINITY;
    float l0 = 0.0f, l1 = 0.0f;

    auto stage = [&](int kb, int buf) {
        const uint32_t kd = ks_u + (uint32_t)buf * TILE_H * 2;
        const uint32_t vd = vs_u + (uint32_t)buf * TILE_H * 2;
        #pragma unroll
        for (int i = 0; i < 2; i++) {
            const int chunk = tid + i * 256;
            const int row = chunk >> 3;
            const int c   = chunk & 7;
            cp16(kd + (uint32_t)(row * AST) * 2 + c * 16,
                 kh + (size_t)(kb * 64 + row) * C_DIM + h * 64 + c * 8);
            cp16(vd + (uint32_t)(row * AST) * 2 + c * 16,
                 vt + (size_t)(h * 64 + row) * T_SEQ + kb * 64 + c * 8);
        }
        CP_COMMIT();
    };

    stage(0, 0);

    #pragma unroll 1
    for (int kb = 0; kb < T_SEQ / 64; kb++) {
        const int cur = kb & 1;
        asm volatile("cp.async.wait_group 0;" ::: "memory");
        __syncthreads();
        if (kb + 1 < T_SEQ / 64) stage(kb + 1, cur ^ 1);

        const uint32_t kbase = ks_u + (uint32_t)cur * TILE_H * 2 + ldsm_off;
        const uint32_t vbase = vs_u + (uint32_t)cur * TILE_H * 2 + ldsm_off;

        float p[8][4];
        #pragma unroll
        for (int nt = 0; nt < 8; nt++)
            #pragma unroll
            for (int i = 0; i < 4; i++) p[nt][i] = 0.0f;

        #pragma unroll
        for (int ks = 0; ks < 4; ks++) {
            #pragma unroll
            for (int pp = 0; pp < 4; pp++) {
                unsigned b0, b1, b2, b3;
                ldsm_x4(b0, b1, b2, b3,
                        kbase + (uint32_t)((pp * 16 * AST + ks * 16) * 2));
                unsigned bfa[2] = {b0, b1};
                unsigned bfb[2] = {b2, b3};
                mma_f16(p[2 * pp],     qa[ks], bfa);
                mma_f16(p[2 * pp + 1], qa[ks], bfb);
            }
        }

        float mx0 = -INFINITY, mx1 = -INFINITY;
        #pragma unroll
        for (int nt = 0; nt < 8; nt++) {
            mx0 = fmaxf(mx0, fmaxf(p[nt][0], p[nt][1]));
            mx1 = fmaxf(mx1, fmaxf(p[nt][2], p[nt][3]));
        }
        #pragma unroll
        for (int off = 1; off < 4; off <<= 1) {
            mx0 = fmaxf(mx0, __shfl_xor_sync(0xffffffffu, mx0, off));
            mx1 = fmaxf(mx1, __shfl_xor_sync(0xffffffffu, mx1, off));
        }
        const float nm0 = fmaxf(m0, mx0);
        const float nm1 = fmaxf(m1, mx1);
        const float al0 = ex2f(m0 - nm0);
        const float al1 = ex2f(m1 - nm1);
        m0 = nm0; m1 = nm1;

        float rs0 = 0.0f, rs1 = 0.0f;
        #pragma unroll
        for (int nt = 0; nt < 8; nt++) {
            p[nt][0] = ex2f(p[nt][0] - m0);
            p[nt][1] = ex2f(p[nt][1] - m0);
            p[nt][2] = ex2f(p[nt][2] - m1);
            p[nt][3] = ex2f(p[nt][3] - m1);
            rs0 += p[nt][0] + p[nt][1];
            rs1 += p[nt][2] + p[nt][3];
        }
        l0 = l0 * al0 + rs0;
        l1 = l1 * al1 + rs1;

        if (__any_sync(0xffffffffu, (al0 < 1.0f) || (al1 < 1.0f))) {
            #pragma unroll
            for (int nt = 0; nt < 8; nt++) {
                o[nt][0] *= al0; o[nt][1] *= al0;
                o[nt][2] *= al1; o[nt][3] *= al1;
            }
        }

        #pragma unroll
        for (int ks = 0; ks < 4; ks++) {
            unsigned af[4];
            __half2 t0 = __floats2half2_rn(p[2 * ks][0],     p[2 * ks][1]);
            __half2 t1 = __floats2half2_rn(p[2 * ks][2],     p[2 * ks][3]);
            __half2 t2 = __floats2half2_rn(p[2 * ks + 1][0], p[2 * ks + 1][1]);
            __half2 t3 = __floats2half2_rn(p[2 * ks + 1][2], p[2 * ks + 1][3]);
            af[0] = *(unsigned*)&t0;
            af[1] = *(unsigned*)&t1;
            af[2] = *(unsigned*)&t2;
            af[3] = *(unsigned*)&t3;
            #pragma unroll
            for (int pt = 0; pt < 4; pt++) {
                unsigned b0, b1, b2, b3;
                ldsm_x4(b0, b1, b2, b3,
                        vbase + (uint32_t)((pt * 16 * AST + ks * 16) * 2));
                unsigned bfa[2] = {b0, b1};
                unsigned bfb[2] = {b2, b3};
                mma_f16(o[2 * pt],     af, bfa);
                mma_f16(o[2 * pt + 1], af, bfb);
            }
        }
    }

    #pragma unroll
    for (int off = 1; off < 4; off <<= 1) {
        l0 += __shfl_xor_sync(0xffffffffu, l0, off);
        l1 += __shfl_xor_sync(0xffffffffu, l1, off);
    }
    const float il0 = 1.0f / l0;
    const float il1 = 1.0f / l1;
    __half* op0 = attn_out + (size_t)qrow * C_DIM + h * 64;
    __half* op1 = op0 + (size_t)8 * C_DIM;
    #pragma unroll
    for (int nt = 0; nt < 8; nt++) {
        const int col = nt * 8 + 2 * q;
        *(__half2*)(op0 + col) = __floats2half2_rn(o[nt][0] * il0, o[nt][1] * il0);
        *(__half2*)(op1 + col) = __floats2half2_rn(o[nt][2] * il1, o[nt][3] * il1);
    }
}

// ---------------------------------------------------------------------------
extern "C" void kernel_launch(void* const* d_in, const int* in_sizes, int n_in,
                              void* d_out, int out_size)
{
    const float* x    = (const float*)d_in[0];
    const float* Wqkv = (const float*)d_in[1];
    const float* bqkv = (const float*)d_in[2];
    const float* Wout = (const float*)d_in[3];
    const float* bout = (const float*)d_in[4];
    float* out = (float*)d_out;

    __half *xh, *wqh, *woh, *qh, *kh, *vt, *ao;
    cudaGetSymbolAddress((void**)&xh,  g_xh);
    cudaGetSymbolAddress((void**)&wqh, g_wqh);
    cudaGetSymbolAddress((void**)&woh, g_woh);
    cudaGetSymbolAddress((void**)&qh,  g_qh);
    cudaGetSymbolAddress((void**)&kh,  g_kh);
    cudaGetSymbolAddress((void**)&vt,  g_vt);
    cudaGetSymbolAddress((void**)&ao,  g_ao);

    cudaFuncSetAttribute(gemm_f16, cudaFuncAttributeMaxDynamicSharedMemorySize,
                         GEMM_SMEM_BYTES);
    cudaFuncSetAttribute(attn_f16, cudaFuncAttributeMaxDynamicSharedMemorySize,
                         ATTN_SMEM_BYTES);

    // 0) fused prepass: fp32 -> fp16 for x, W_qkv, W_out in ONE launch
    cvt_all_kernel<<<(N8_TOT + 255) / 256, 256>>>(
        (const float4*)x, (const float4*)Wqkv, (const float4*)Wout,
        (uint4*)xh, (uint4*)wqh, (uint4*)woh);

    // 1) QKV projection (fp16 mma) -> fp16 Q/K/V (V head-transposed)
    gemm_f16<<<dim3(QKV_N / GBN, T_SEQ / GBM), 256, GEMM_SMEM_BYTES>>>(
        xh, wqh, bqkv, nullptr, T_SEQ, QKV_N, C_DIM, 1, qh, kh, vt);

    // 2) Multi-head flash attention -> fp16 output
    attn_f16<<<dim3(T_SEQ / 128, H_NUM), 256, ATTN_SMEM_BYTES>>>(qh, kh, vt, ao);

    // 3) Output projection (fp16 mma, fp32 out)
    gemm_f16<<<dim3(C_DIM / GBN, T_SEQ / GBM), 256, GEMM_SMEM_BYTES>>>(
        ao, woh, bout, out, T_SEQ, C_DIM, C_DIM, 0,
        nullptr, nullptr, nullptr);
}